// round 17
// baseline (speedup 1.0000x reference)
#include <cuda_runtime.h>
#include <cstdint>

#define TT   128
#define BLK  128
#define EPB  64          // elements per block: 4 warps x 16
#define RSTRIDE 220      // floats per role block in shared

// role blocks: 0=lstm1, 1=lstm2a, 2=lstm2b, 3=zeros (dummy)
#define FC_OFF 880
#define FW1 (FC_OFF)
#define FB1 (FW1+640)
#define FW2 (FB1+32)
#define FB2 (FW2+1024)
#define FW3 (FB2+32)
#define FB3 (FW3+512)
#define FW4 (FB3+16)
#define FB4 (FW4+256)
#define FW5 (FB4+16)
#define FB5 (FW5+80)
#define S_TOTAL (FB5+5)   // 3713 floats = ~14.9 KB

typedef unsigned long long u64;

__device__ __forceinline__ float tanh_fast(float x) {
    float y;
    asm("tanh.approx.f32 %0, %1;" : "=f"(y) : "f"(x));
    return y;
}
// rows pre-scaled by 0.5 at staging: sigm(a) = fma(tanh(a'), 0.5, 0.5)
__device__ __forceinline__ float sigm_pre(float a_half) {
    return fmaf(tanh_fast(a_half), 0.5f, 0.5f);
}

__device__ __forceinline__ u64 ffma2(u64 a, u64 b, u64 c) {
    u64 d;
    asm("fma.rn.f32x2 %0, %1, %2, %3;" : "=l"(d) : "l"(a), "l"(b), "l"(c));
    return d;
}
__device__ __forceinline__ u64 bcast2(float x) {
    u64 d;
    asm("mov.b64 %0, {%1, %1};" : "=l"(d) : "f"(x));
    return d;
}
__device__ __forceinline__ void unpack2(u64 v, float& lo, float& hi) {
    asm("mov.b64 {%0, %1}, %2;" : "=f"(lo), "=f"(hi) : "l"(v));
}

// activation tail shared by both cell variants
__device__ __forceinline__ void act_update(u64* __restrict__ g,
                                           float* __restrict__ h,
                                           float* __restrict__ c) {
    float ga[20];
    #pragma unroll
    for (int q = 0; q < 10; q++) unpack2(g[q], ga[2*q], ga[2*q+1]);
    #pragma unroll
    for (int m = 0; m < 5; m++) {
        float ig = sigm_pre(ga[m]);
        float fg = sigm_pre(ga[5 + m]);
        float gg = tanh_fast(ga[10 + m]);
        float og = sigm_pre(ga[15 + m]);
        float cm = fmaf(fg, c[m], ig * gg);
        c[m] = cm;
        h[m] = og * tanh_fast(cm);
    }
}

__device__ __forceinline__ void gate_fma(const float* __restrict__ base,
                                         u64 v2, u64* __restrict__ g) {
    const ulonglong2* w2 = reinterpret_cast<const ulonglong2*>(base);
    #pragma unroll
    for (int q = 0; q < 5; q++) {
        ulonglong2 w = w2[q];
        g[2*q]   = ffma2(w.x, v2, g[2*q]);
        g[2*q+1] = ffma2(w.y, v2, g[2*q+1]);
    }
}

// cell with bias in registers (slot1). Bias folded into the k=0 FMA.
__device__ __forceinline__ void cellr(const float* __restrict__ sW,
                                      const u64* __restrict__ bias2,
                                      const float* __restrict__ in,
                                      float* __restrict__ h,
                                      float* __restrict__ c) {
    u64 g[10];
    {
        u64 x0 = bcast2(in[0]);
        const ulonglong2* w2 = reinterpret_cast<const ulonglong2*>(sW);
        #pragma unroll
        for (int q = 0; q < 5; q++) {
            ulonglong2 w = w2[q];
            g[2*q]   = ffma2(w.x, x0, bias2[2*q]);
            g[2*q+1] = ffma2(w.y, x0, bias2[2*q+1]);
        }
    }
    #pragma unroll
    for (int k = 1; k < 5; k++) gate_fma(sW + k * 20, bcast2(in[k]), g);
    #pragma unroll
    for (int k = 0; k < 5; k++) gate_fma(sW + 100 + k * 20, bcast2(h[k]), g);
    act_update(g, h, c);
}

// cell with bias from shared (slot2)
__device__ __forceinline__ void cells(const float* __restrict__ sW,
                                      const float* __restrict__ sB,
                                      const float* __restrict__ in,
                                      float* __restrict__ h,
                                      float* __restrict__ c) {
    u64 g[10];
    {
        const ulonglong2* b2 = reinterpret_cast<const ulonglong2*>(sB);
        #pragma unroll
        for (int q = 0; q < 5; q++) {
            ulonglong2 v = b2[q];
            g[2*q] = v.x; g[2*q+1] = v.y;
        }
    }
    #pragma unroll
    for (int k = 0; k < 5; k++) gate_fma(sW + k * 20, bcast2(in[k]), g);
    #pragma unroll
    for (int k = 0; k < 5; k++) gate_fma(sW + 100 + k * 20, bcast2(h[k]), g);
    act_update(g, h, c);
}

// Load one 2-timestep chunk (10 floats, 8B-aligned) with LDG.64.
__device__ __forceinline__ void load2(float* dst, const float* src) {
    const float2* s2 = reinterpret_cast<const float2*>(src);
    #pragma unroll
    for (int i = 0; i < 5; i++) {
        float2 v = __ldg(s2 + i);
        dst[2*i+0] = v.x; dst[2*i+1] = v.y;
    }
}

struct Params {
    const float *x1, *x2;
    const float *Wih1, *Whh1, *bih1, *bhh1;
    const float *Wih2a, *Whh2a, *bih2a, *bhh2a;
    const float *Wih2b, *Whh2b, *bih2b, *bhh2b;
    const float *W1, *b1, *W2, *b2, *W3, *b3, *W4, *b4, *W5, *b5;
    float* out;
    int B;
};

__global__ __launch_bounds__(BLK, 2)
void dynrnn_kernel(Params p) {
    __shared__ float s[S_TOTAL];
    const int tid = threadIdx.x;

    // ---- cooperative weight staging ----
    // sigmoid-gate rows (j<10 i/f, j>=15 o) pre-scaled by 0.5
    {
        const float* srcs[6] = { p.Wih1, p.Whh1, p.Wih2a, p.Whh2a, p.Wih2b, p.Whh2b };
        const int    offs[6] = { 0, 100, RSTRIDE, RSTRIDE+100, 2*RSTRIDE, 2*RSTRIDE+100 };
        for (int m = 0; m < 6; m++) {
            const float* W = srcs[m];
            int off = offs[m];
            for (int i = tid; i < 100; i += BLK) {
                int j = i / 5, k = i % 5;
                float sc = (j < 10 || j >= 15) ? 0.5f : 1.0f;
                s[off + k * 20 + j] = W[i] * sc;
            }
        }
        for (int i = tid; i < 20; i += BLK) {
            float sc = (i < 10 || i >= 15) ? 0.5f : 1.0f;
            s[0*RSTRIDE + 200 + i] = (p.bih1[i]  + p.bhh1[i])  * sc;
            s[1*RSTRIDE + 200 + i] = (p.bih2a[i] + p.bhh2a[i]) * sc;
            s[2*RSTRIDE + 200 + i] = (p.bih2b[i] + p.bhh2b[i]) * sc;
        }
        // role block 3: zeros (dummy cell)
        for (int i = tid; i < RSTRIDE; i += BLK) s[3*RSTRIDE + i] = 0.0f;
        for (int i = tid; i < 640;  i += BLK) s[FW1 + i] = p.W1[i];
        for (int i = tid; i < 32;   i += BLK) s[FB1 + i] = p.b1[i];
        for (int i = tid; i < 1024; i += BLK) s[FW2 + i] = p.W2[i];
        for (int i = tid; i < 32;   i += BLK) s[FB2 + i] = p.b2[i];
        for (int i = tid; i < 512;  i += BLK) s[FW3 + i] = p.W3[i];
        for (int i = tid; i < 16;   i += BLK) s[FB3 + i] = p.b3[i];
        for (int i = tid; i < 256;  i += BLK) s[FW4 + i] = p.W4[i];
        for (int i = tid; i < 16;   i += BLK) s[FB4 + i] = p.b4[i];
        for (int i = tid; i < 80;   i += BLK) s[FW5 + i] = p.W5[i];
        for (int i = tid; i < 5;    i += BLK) s[FB5 + i] = p.b5[i];
    }
    __syncthreads();

    // ---- lane mapping: 2 lanes per element, 16 elements per warp ----
    // even lane: slot1 = lstm1(e) [x1], slot2 = lstm2b(e) [nh from odd lane, 1 step behind]
    // odd  lane: slot1 = lstm2a(e) [x2], slot2 = dummy (zero weights)
    const int l   = tid & 31;
    const int sub = l & 1;
    const int pr  = l >> 1;          // 0..15

    const int e = blockIdx.x * EPB + (tid >> 5) * 16 + pr;
    const bool valid = (e < p.B);
    const int ec = valid ? e : (p.B - 1);

    const bool odd = (sub == 1);
    const float* __restrict__ xp = (odd ? p.x2 : p.x1) + (size_t)ec * (TT * 5);
    const float* __restrict__ sW1 = s + (odd ? RSTRIDE : 0);
    const float* __restrict__ sW2 = s + (odd ? 3 * RSTRIDE : 2 * RSTRIDE);
    const float* __restrict__ sB2 = sW2 + 200;

    // slot1 bias in registers (packed pairs)
    u64 bias1[10];
    {
        const ulonglong2* b2 = reinterpret_cast<const ulonglong2*>(sW1 + 200);
        #pragma unroll
        for (int q = 0; q < 5; q++) {
            ulonglong2 v = b2[q];
            bias1[2*q] = v.x; bias1[2*q+1] = v.y;
        }
    }

    float h1[5], c1[5], h2[5], c2[5], nh[5];
    #pragma unroll
    for (int m = 0; m < 5; m++) {
        h1[m] = 0.0f; c1[m] = 0.0f; h2[m] = 0.0f; c2[m] = 0.0f; nh[m] = 0.0f;
    }

    float A[10], Bb[10];  // 2-step x double buffers
    load2(A, xp);         // chunk 0 (steps 0,1)

    // ---- peeled it=0 (chunks 0,1 = steps 0..3) with slot2 warm-up reset ----
    {
        load2(Bb, xp + 10);
        // step 0: slot1 only (slot2 has nothing valid to consume)
        cellr(sW1, bias1, &A[0], h1, c1);
        #pragma unroll
        for (int j = 0; j < 5; j++) nh[j] = __shfl_down_sync(0xFFFFFFFFu, h1[j], 1);
        // step 1: slot2 consumes h2a(0) -> lstm2b(0); slot1 advances
        cells(sW2, sB2, nh, h2, c2);
        cellr(sW1, bias1, &A[5], h1, c1);
        #pragma unroll
        for (int j = 0; j < 5; j++) nh[j] = __shfl_down_sync(0xFFFFFFFFu, h1[j], 1);
        load2(A, xp + 20);
        // steps 2,3 from Bb
        #pragma unroll
        for (int tl = 0; tl < 2; tl++) {
            cells(sW2, sB2, nh, h2, c2);
            cellr(sW1, bias1, &Bb[tl * 5], h1, c1);
            #pragma unroll
            for (int j = 0; j < 5; j++) nh[j] = __shfl_down_sync(0xFFFFFFFFu, h1[j], 1);
        }
    }

    // ---- main loop it=1..15: chunks 2it..2it+1 (4 steps each) ----
    #pragma unroll 1
    for (int it = 1; it < 32; it++) {
        load2(Bb, xp + (2 * it + 1) * 10);
        #pragma unroll
        for (int tl = 0; tl < 2; tl++) {
            cells(sW2, sB2, nh, h2, c2);
            cellr(sW1, bias1, &A[tl * 5], h1, c1);
            #pragma unroll
            for (int j = 0; j < 5; j++) nh[j] = __shfl_down_sync(0xFFFFFFFFu, h1[j], 1);
        }
        int ci = 2 * it + 2; if (ci > 63) ci = 63;  // clamped redundant load on last iter
        load2(A, xp + ci * 10);
        #pragma unroll
        for (int tl = 0; tl < 2; tl++) {
            cells(sW2, sB2, nh, h2, c2);
            cellr(sW1, bias1, &Bb[tl * 5], h1, c1);
            #pragma unroll
            for (int j = 0; j < 5; j++) nh[j] = __shfl_down_sync(0xFFFFFFFFu, h1[j], 1);
        }
    }
    // after loop: slot1 done through step 127; slot2 (lstm2b) through step 126;
    // nh = h2a(127) on even lanes; Bb = chunk 63 (steps 126,127)

    // drain: lstm2b(127)
    cells(sW2, sB2, nh, h2, c2);

    // ---- gather x2 last from odd lane ----
    float x2l[5];
    #pragma unroll
    for (int j = 0; j < 5; j++) {
        x2l[j] = __shfl_down_sync(0xFFFFFFFFu, Bb[5 + j], 1);
    }

    if (valid && sub == 0) {
        float a0[20];
        #pragma unroll
        for (int j = 0; j < 5; j++) {
            a0[j]      = Bb[5 + j];  // x1 last
            a0[5 + j]  = x2l[j];     // x2 last
            a0[10 + j] = h1[j];      // out1 (lstm1)
            a0[15 + j] = h2[j];      // out2 (lstm2b)
        }
        float a1[32];
        #pragma unroll
        for (int j = 0; j < 32; j++) {
            float acc = s[FB1 + j];
            #pragma unroll
            for (int k = 0; k < 20; k++) acc = fmaf(s[FW1 + j * 20 + k], a0[k], acc);
            a1[j] = fmaxf(acc, 0.0f);
        }
        float a2[32];
        #pragma unroll
        for (int j = 0; j < 32; j++) {
            float acc = s[FB2 + j];
            #pragma unroll
            for (int k = 0; k < 32; k++) acc = fmaf(s[FW2 + j * 32 + k], a1[k], acc);
            a2[j] = fmaxf(acc, 0.0f);
        }
        float a3[16];
        #pragma unroll
        for (int j = 0; j < 16; j++) {
            float acc = s[FB3 + j];
            #pragma unroll
            for (int k = 0; k < 32; k++) acc = fmaf(s[FW3 + j * 32 + k], a2[k], acc);
            a3[j] = fmaxf(acc, 0.0f);
        }
        float a4[16];
        #pragma unroll
        for (int j = 0; j < 16; j++) {
            float acc = s[FB4 + j];
            #pragma unroll
            for (int k = 0; k < 16; k++) acc = fmaf(s[FW4 + j * 16 + k], a3[k], acc);
            a4[j] = fmaxf(acc, 0.0f);
        }
        #pragma unroll
        for (int j = 0; j < 5; j++) {
            float acc = s[FB5 + j];
            #pragma unroll
            for (int k = 0; k < 16; k++) acc = fmaf(s[FW5 + j * 16 + k], a4[k], acc);
            p.out[(size_t)e * 5 + j] = acc;
        }
    }
}

extern "C" void kernel_launch(void* const* d_in, const int* in_sizes, int n_in,
                              void* d_out, int out_size) {
    Params p;
    p.x1    = (const float*)d_in[0];
    p.x2    = (const float*)d_in[1];
    p.Wih1  = (const float*)d_in[2];
    p.Whh1  = (const float*)d_in[3];
    p.bih1  = (const float*)d_in[4];
    p.bhh1  = (const float*)d_in[5];
    p.Wih2a = (const float*)d_in[6];
    p.Whh2a = (const float*)d_in[7];
    p.bih2a = (const float*)d_in[8];
    p.bhh2a = (const float*)d_in[9];
    p.Wih2b = (const float*)d_in[10];
    p.Whh2b = (const float*)d_in[11];
    p.bih2b = (const float*)d_in[12];
    p.bhh2b = (const float*)d_in[13];
    p.W1 = (const float*)d_in[14];  p.b1 = (const float*)d_in[15];
    p.W2 = (const float*)d_in[16];  p.b2 = (const float*)d_in[17];
    p.W3 = (const float*)d_in[18];  p.b3 = (const float*)d_in[19];
    p.W4 = (const float*)d_in[20];  p.b4 = (const float*)d_in[21];
    p.W5 = (const float*)d_in[22];  p.b5 = (const float*)d_in[23];
    p.out = (float*)d_out;
    p.B   = in_sizes[0] / (TT * 5);

    int grid = (p.B + EPB - 1) / EPB;   // 256 blocks for B=16384 -> single wave
    dynrnn_kernel<<<grid, BLK>>>(p);
}